// round 2
// baseline (speedup 1.0000x reference)
#include <cuda_runtime.h>
#include <math.h>

#define N_NODES   65536
#define E_EDGES   2097152
#define FEAT_IN   16
#define HID       32
#define N_GRAPHS  16
#define K_FC      131072      // 4096 * 32
#define FC_HID    256
#define LATENT    64
#define TILE_K    512

// -------- scratch (static device globals; no runtime allocation) --------
__device__ int   g_src[E_EDGES];
__device__ int   g_dst[E_EDGES];
__device__ float g_hA[N_NODES * HID];
__device__ float g_hB[N_NODES * HID];
__device__ float g_agg[N_NODES * HID];
__device__ float g_fc1[N_GRAPHS * FC_HID];
__device__ int   g_is64;

__device__ __forceinline__ float elu(float v) {
    return v > 0.0f ? v : expm1f(v);
}

// -------- detect whether edge_index buffer is int64 or int32 --------
// If int64: every "high word" (odd uint) of the first 1024 pairs is 0
// (indices are < 65536). If int32: odd positions are random node indices,
// essentially never all zero.
__global__ void detect_dtype_kernel(const unsigned int* __restrict__ ei) {
    __shared__ int any_hi;
    if (threadIdx.x == 0) any_hi = 0;
    __syncthreads();
    unsigned int hi = ei[threadIdx.x * 2 + 1];
    if (hi != 0u) atomicOr(&any_hi, 1);
    __syncthreads();
    if (threadIdx.x == 0) g_is64 = (any_hi == 0) ? 1 : 0;
}

// -------- convert edge_index (int64 or int32) -> int32 src/dst --------
__global__ void conv_idx_kernel(const void* __restrict__ eiv) {
    int e = blockIdx.x * blockDim.x + threadIdx.x;
    if (e >= E_EDGES) return;
    if (g_is64) {
        const long long* ei = (const long long*)eiv;
        g_src[e] = (int)ei[e];
        g_dst[e] = (int)ei[E_EDGES + e];
    } else {
        const int* ei = (const int*)eiv;
        g_src[e] = ei[e];
        g_dst[e] = ei[E_EDGES + e];
    }
}

// -------- edge scatter: agg[dst, c] += h[src, c] * w[e] --------
template <int C>
__global__ __launch_bounds__(256)
void scatter_kernel(const float* __restrict__ h, const float* __restrict__ w) {
    int tid = blockIdx.x * blockDim.x + threadIdx.x;   // E*C threads exactly
    int e = tid >> (C == 32 ? 5 : 4);
    int c = tid & (C - 1);
    int s = g_src[e];
    int d = g_dst[e];
    float v = __ldg(&h[s * C + c]) * __ldg(&w[e]);
    atomicAdd(&g_agg[d * C + c], v);
}

// -------- per-node linear + ELU: out[n,:] = elu(agg[n,:] @ W + b) --------
template <int CIN>
__global__ __launch_bounds__(256)
void linear_elu_kernel(const float* __restrict__ W,
                       const float* __restrict__ b,
                       float* __restrict__ out) {
    __shared__ float Ws[CIN * HID];
    __shared__ float bs[HID];
    int tid = threadIdx.x;
    for (int i = tid; i < CIN * HID; i += 256) Ws[i] = W[i];
    if (tid < HID) bs[tid] = b[tid];
    __syncthreads();

    int n = blockIdx.x * 8 + (tid >> 5);
    int j = tid & 31;
    const float* a = &g_agg[n * CIN];
    float acc = bs[j];
#pragma unroll
    for (int k = 0; k < CIN; k++) acc = fmaf(a[k], Ws[k * HID + j], acc);
    out[n * HID + j] = elu(acc);
}

// -------- FC1: g_fc1[16,256] += H[16,131072] @ Wfc1[131072,256] (K-split) --------
__global__ __launch_bounds__(256)
void fc1_kernel(const float* __restrict__ H, const float* __restrict__ Wfc1) {
    __shared__ float Hs[TILE_K * N_GRAPHS];   // [k][m] layout, 32 KB
    int tid = threadIdx.x;
    int k0 = blockIdx.x * TILE_K;

    for (int i = tid; i < TILE_K * N_GRAPHS; i += 256) {
        int m = i / TILE_K;
        int k = i - m * TILE_K;
        Hs[k * N_GRAPHS + m] = H[m * K_FC + k0 + k];   // coalesced global read
    }
    __syncthreads();

    float acc[N_GRAPHS];
#pragma unroll
    for (int m = 0; m < N_GRAPHS; m++) acc[m] = 0.0f;

    for (int k = 0; k < TILE_K; k++) {
        float wv = __ldg(&Wfc1[(k0 + k) * FC_HID + tid]);   // coalesced
        const float4* hp = (const float4*)&Hs[k * N_GRAPHS]; // warp-uniform -> broadcast
        float4 h0 = hp[0], h1 = hp[1], h2 = hp[2], h3 = hp[3];
        acc[0]  = fmaf(h0.x, wv, acc[0]);
        acc[1]  = fmaf(h0.y, wv, acc[1]);
        acc[2]  = fmaf(h0.z, wv, acc[2]);
        acc[3]  = fmaf(h0.w, wv, acc[3]);
        acc[4]  = fmaf(h1.x, wv, acc[4]);
        acc[5]  = fmaf(h1.y, wv, acc[5]);
        acc[6]  = fmaf(h1.z, wv, acc[6]);
        acc[7]  = fmaf(h1.w, wv, acc[7]);
        acc[8]  = fmaf(h2.x, wv, acc[8]);
        acc[9]  = fmaf(h2.y, wv, acc[9]);
        acc[10] = fmaf(h2.z, wv, acc[10]);
        acc[11] = fmaf(h2.w, wv, acc[11]);
        acc[12] = fmaf(h3.x, wv, acc[12]);
        acc[13] = fmaf(h3.y, wv, acc[13]);
        acc[14] = fmaf(h3.z, wv, acc[14]);
        acc[15] = fmaf(h3.w, wv, acc[15]);
    }
#pragma unroll
    for (int m = 0; m < N_GRAPHS; m++)
        atomicAdd(&g_fc1[m * FC_HID + tid], acc[m]);
}

// -------- FC2: out[16,64] = elu(g_fc1 + bfc1) @ Wfc2 + bfc2 --------
__global__ __launch_bounds__(1024)
void fc2_kernel(const float* __restrict__ bfc1,
                const float* __restrict__ Wfc2,
                const float* __restrict__ bfc2,
                float* __restrict__ out) {
    __shared__ float s[N_GRAPHS * FC_HID];   // 16 KB
    int tid = threadIdx.x;
    for (int i = tid; i < N_GRAPHS * FC_HID; i += 1024) {
        float v = g_fc1[i] + bfc1[i & (FC_HID - 1)];
        s[i] = elu(v);
    }
    __syncthreads();

    int m = tid >> 6;
    int j = tid & 63;
    float acc = bfc2[j];
#pragma unroll 8
    for (int k = 0; k < FC_HID; k++)
        acc = fmaf(s[m * FC_HID + k], __ldg(&Wfc2[k * LATENT + j]), acc);
    out[m * LATENT + j] = acc;
}

extern "C" void kernel_launch(void* const* d_in, const int* in_sizes, int n_in,
                              void* d_out, int out_size) {
    // ---- size-based input mapping (ordering-agnostic) ----
    const float *x = 0, *ea = 0, *W1 = 0, *Wfc1 = 0, *bfc1 = 0, *Wfc2 = 0, *bfc2 = 0;
    const float *Wh[2] = {0, 0};       // W2, W3 (both 1024 elems, relative order kept)
    const float *bh[3] = {0, 0, 0};    // b1, b2, b3 (all 32 elems, relative order kept)
    const void  *ei = 0;
    int nWh = 0, nbh = 0;
    for (int i = 0; i < n_in; i++) {
        switch (in_sizes[i]) {
            case 1048576:  x    = (const float*)d_in[i]; break;  // 65536*16
            case 2097152:  ea   = (const float*)d_in[i]; break;  // E
            case 512:      W1   = (const float*)d_in[i]; break;  // 16*32
            case 1024:     if (nWh < 2) Wh[nWh++] = (const float*)d_in[i]; break;
            case 32:       if (nbh < 3) bh[nbh++] = (const float*)d_in[i]; break;
            case 33554432: Wfc1 = (const float*)d_in[i]; break;  // 131072*256
            case 256:      bfc1 = (const float*)d_in[i]; break;
            case 16384:    Wfc2 = (const float*)d_in[i]; break;  // 256*64
            case 64:       bfc2 = (const float*)d_in[i]; break;
            case 4194304:  ei   = d_in[i]; break;                // 2*E
            default: break;
        }
    }
    const float *W2 = Wh[0], *W3 = Wh[1];
    const float *b1 = bh[0], *b2 = bh[1], *b3 = bh[2];
    float* out = (float*)d_out;

    void *aggp, *fc1p, *hAp, *hBp;
    cudaGetSymbolAddress(&aggp, g_agg);
    cudaGetSymbolAddress(&fc1p, g_fc1);
    cudaGetSymbolAddress(&hAp, g_hA);
    cudaGetSymbolAddress(&hBp, g_hB);

    // index dtype detection + conversion
    detect_dtype_kernel<<<1, 1024>>>((const unsigned int*)ei);
    conv_idx_kernel<<<E_EDGES / 256, 256>>>(ei);

    // ---- layer 1: x[N,16] -> hA[N,32] ----
    cudaMemsetAsync(aggp, 0, (size_t)N_NODES * FEAT_IN * sizeof(float));
    scatter_kernel<16><<<(E_EDGES * 16) / 256, 256>>>(x, ea);
    linear_elu_kernel<16><<<N_NODES / 8, 256>>>(W1, b1, (float*)hAp);

    // ---- layer 2: hA -> hB ----
    cudaMemsetAsync(aggp, 0, (size_t)N_NODES * HID * sizeof(float));
    scatter_kernel<32><<<(E_EDGES * 32) / 256, 256>>>((const float*)hAp, ea);
    linear_elu_kernel<32><<<N_NODES / 8, 256>>>(W2, b2, (float*)hBp);

    // ---- layer 3: hB -> hA ----
    cudaMemsetAsync(aggp, 0, (size_t)N_NODES * HID * sizeof(float));
    scatter_kernel<32><<<(E_EDGES * 32) / 256, 256>>>((const float*)hBp, ea);
    linear_elu_kernel<32><<<N_NODES / 8, 256>>>(W3, b3, (float*)hAp);

    // ---- FC1 ----
    cudaMemsetAsync(fc1p, 0, (size_t)N_GRAPHS * FC_HID * sizeof(float));
    fc1_kernel<<<K_FC / TILE_K, 256>>>((const float*)hAp, Wfc1);

    // ---- FC2 -> output ----
    fc2_kernel<<<1, 1024>>>(bfc1, Wfc2, bfc2, out);
}

// round 3
// speedup vs baseline: 1.7425x; 1.7425x over previous
#include <cuda_runtime.h>
#include <math.h>

#define N_NODES   65536
#define E_EDGES   2097152
#define FEAT_IN   16
#define HID       32
#define N_GRAPHS  16
#define K_FC      131072      // 4096 * 32
#define FC_HID    256
#define LATENT    64
#define TILE_K    512

// -------- scratch (static device globals; no runtime allocation) --------
__device__ float2 g_es[E_EDGES];           // packed (src_as_float_bits, w), sorted by dst
__device__ int    g_cnt[N_NODES];
__device__ int    g_rowptr[N_NODES + 1];
__device__ int    g_cursor[N_NODES];
__device__ int    g_bsum[64];
__device__ float  g_hA[N_NODES * HID];
__device__ float  g_hB[N_NODES * HID];
__device__ float  g_fc1[N_GRAPHS * FC_HID];
__device__ int    g_is64;

__device__ __forceinline__ float elu(float v) {
    return v > 0.0f ? v : expm1f(v);
}

// -------- detect whether edge_index buffer is int64 or int32 --------
__global__ void detect_dtype_kernel(const unsigned int* __restrict__ ei) {
    __shared__ int any_hi;
    if (threadIdx.x == 0) any_hi = 0;
    __syncthreads();
    unsigned int hi = ei[threadIdx.x * 2 + 1];
    if (hi != 0u) atomicOr(&any_hi, 1);
    __syncthreads();
    if (threadIdx.x == 0) g_is64 = (any_hi == 0) ? 1 : 0;
}

__device__ __forceinline__ int load_idx(const void* eiv, long long pos) {
    if (g_is64) return (int)((const long long*)eiv)[pos];
    return ((const int*)eiv)[pos];
}

// -------- CSR build: count incoming edges per dst --------
__global__ __launch_bounds__(256)
void count_kernel(const void* __restrict__ eiv) {
    int e = blockIdx.x * blockDim.x + threadIdx.x;
    if (e < E_EDGES) {
        int d = load_idx(eiv, (long long)E_EDGES + e);
        atomicAdd(&g_cnt[d], 1);
    }
}

// -------- scan pass 1: per-1024 block inclusive scan -> local exclusive --------
__global__ __launch_bounds__(1024)
void scan1_kernel() {
    __shared__ int s[1024];
    int tid = threadIdx.x;
    int i = blockIdx.x * 1024 + tid;
    int v = g_cnt[i];
    s[tid] = v;
    __syncthreads();
#pragma unroll
    for (int off = 1; off < 1024; off <<= 1) {
        int t = (tid >= off) ? s[tid - off] : 0;
        __syncthreads();
        s[tid] += t;
        __syncthreads();
    }
    g_rowptr[i] = s[tid] - v;               // local exclusive
    if (tid == 1023) g_bsum[blockIdx.x] = s[1023];
}

// -------- scan pass 2: add block prefix, init cursors --------
__global__ __launch_bounds__(1024)
void scan2_kernel() {
    __shared__ int bp;
    int tid = threadIdx.x;
    if (tid == 0) {
        int acc = 0;
        for (int j = 0; j < (int)blockIdx.x; j++) acc += g_bsum[j];
        bp = acc;
    }
    __syncthreads();
    int i = blockIdx.x * 1024 + tid;
    int v = g_rowptr[i] + bp;
    g_rowptr[i] = v;
    g_cursor[i] = v;
    if (i == N_NODES - 1) g_rowptr[N_NODES] = E_EDGES;
}

// -------- CSR fill: bucket edges by dst, pack (src, w) --------
__global__ __launch_bounds__(256)
void fill_kernel(const void* __restrict__ eiv, const float* __restrict__ w) {
    int e = blockIdx.x * blockDim.x + threadIdx.x;
    if (e < E_EDGES) {
        int s = load_idx(eiv, e);
        int d = load_idx(eiv, (long long)E_EDGES + e);
        int p = atomicAdd(&g_cursor[d], 1);
        g_es[p] = make_float2(__int_as_float(s), w[e]);
    }
}

// -------- fused: agg[n] = sum_{e in CSR[n]} h[src_e]*w_e ; out = elu(agg@W+b) --------
template <int CIN>
__global__ __launch_bounds__(256)
void agg_linear_kernel(const float* __restrict__ h,
                       const float* __restrict__ W,
                       const float* __restrict__ b,
                       float* __restrict__ out) {
    __shared__ float Ws[CIN * HID];
    __shared__ float bs[HID];
    int tid = threadIdx.x;
    for (int i = tid; i < CIN * HID; i += 256) Ws[i] = W[i];
    if (tid < HID) bs[tid] = b[tid];
    __syncthreads();

    int n = blockIdx.x * 8 + (tid >> 5);    // one warp per dst node
    int lane = tid & 31;
    int e0 = g_rowptr[n];
    int e1 = g_rowptr[n + 1];

    float acc = 0.0f;
    float2 sw = (e0 < e1) ? g_es[e0] : make_float2(0.0f, 0.0f);
    for (int e = e0; e < e1; e++) {
        float2 cur = sw;
        if (e + 1 < e1) sw = g_es[e + 1];   // prefetch next edge (uniform 8B)
        int src = __float_as_int(cur.x);
        if (CIN == 32) {
            acc = fmaf(__ldg(&h[src * 32 + lane]), cur.y, acc);
        } else {
            if (lane < CIN) acc = fmaf(__ldg(&h[src * CIN + lane]), cur.y, acc);
        }
    }

    // in-warp linear: out[n][lane] = b[lane] + sum_k acc_k * W[k][lane]
    float o = bs[lane];
#pragma unroll
    for (int k = 0; k < CIN; k++) {
        float ak = __shfl_sync(0xffffffffu, acc, k);
        o = fmaf(ak, Ws[k * HID + lane], o);
    }
    out[n * HID + lane] = elu(o);
}

// -------- FC1: g_fc1[16,256] += H[16,131072] @ Wfc1[131072,256] (K-split) --------
__global__ __launch_bounds__(256)
void fc1_kernel(const float* __restrict__ H, const float* __restrict__ Wfc1) {
    __shared__ float Hs[TILE_K * N_GRAPHS];   // [k][m] layout, 32 KB
    int tid = threadIdx.x;
    int k0 = blockIdx.x * TILE_K;

    for (int i = tid; i < TILE_K * N_GRAPHS; i += 256) {
        int m = i / TILE_K;
        int k = i - m * TILE_K;
        Hs[k * N_GRAPHS + m] = H[m * K_FC + k0 + k];   // coalesced global read
    }
    __syncthreads();

    float acc[N_GRAPHS];
#pragma unroll
    for (int m = 0; m < N_GRAPHS; m++) acc[m] = 0.0f;

    for (int k = 0; k < TILE_K; k++) {
        float wv = __ldg(&Wfc1[(k0 + k) * FC_HID + tid]);     // coalesced
        const float4* hp = (const float4*)&Hs[k * N_GRAPHS];  // warp-uniform -> broadcast
        float4 h0 = hp[0], h1 = hp[1], h2 = hp[2], h3 = hp[3];
        acc[0]  = fmaf(h0.x, wv, acc[0]);
        acc[1]  = fmaf(h0.y, wv, acc[1]);
        acc[2]  = fmaf(h0.z, wv, acc[2]);
        acc[3]  = fmaf(h0.w, wv, acc[3]);
        acc[4]  = fmaf(h1.x, wv, acc[4]);
        acc[5]  = fmaf(h1.y, wv, acc[5]);
        acc[6]  = fmaf(h1.z, wv, acc[6]);
        acc[7]  = fmaf(h1.w, wv, acc[7]);
        acc[8]  = fmaf(h2.x, wv, acc[8]);
        acc[9]  = fmaf(h2.y, wv, acc[9]);
        acc[10] = fmaf(h2.z, wv, acc[10]);
        acc[11] = fmaf(h2.w, wv, acc[11]);
        acc[12] = fmaf(h3.x, wv, acc[12]);
        acc[13] = fmaf(h3.y, wv, acc[13]);
        acc[14] = fmaf(h3.z, wv, acc[14]);
        acc[15] = fmaf(h3.w, wv, acc[15]);
    }
#pragma unroll
    for (int m = 0; m < N_GRAPHS; m++)
        atomicAdd(&g_fc1[m * FC_HID + tid], acc[m]);
}

// -------- FC2: out[16,64] = elu(g_fc1 + bfc1) @ Wfc2 + bfc2 --------
__global__ __launch_bounds__(1024)
void fc2_kernel(const float* __restrict__ bfc1,
                const float* __restrict__ Wfc2,
                const float* __restrict__ bfc2,
                float* __restrict__ out) {
    __shared__ float s[N_GRAPHS * FC_HID];   // 16 KB
    int tid = threadIdx.x;
    for (int i = tid; i < N_GRAPHS * FC_HID; i += 1024) {
        float v = g_fc1[i] + bfc1[i & (FC_HID - 1)];
        s[i] = elu(v);
    }
    __syncthreads();

    int m = tid >> 6;
    int j = tid & 63;
    float acc = bfc2[j];
#pragma unroll 8
    for (int k = 0; k < FC_HID; k++)
        acc = fmaf(s[m * FC_HID + k], __ldg(&Wfc2[k * LATENT + j]), acc);
    out[m * LATENT + j] = acc;
}

extern "C" void kernel_launch(void* const* d_in, const int* in_sizes, int n_in,
                              void* d_out, int out_size) {
    // ---- size-based input mapping (ordering-agnostic) ----
    const float *x = 0, *ea = 0, *W1 = 0, *Wfc1 = 0, *bfc1 = 0, *Wfc2 = 0, *bfc2 = 0;
    const float *Wh[2] = {0, 0};       // W2, W3 (both 1024 elems, relative order kept)
    const float *bh[3] = {0, 0, 0};    // b1, b2, b3 (all 32 elems, relative order kept)
    const void  *ei = 0;
    int nWh = 0, nbh = 0;
    for (int i = 0; i < n_in; i++) {
        switch (in_sizes[i]) {
            case 1048576:  x    = (const float*)d_in[i]; break;  // 65536*16
            case 2097152:  ea   = (const float*)d_in[i]; break;  // E
            case 512:      W1   = (const float*)d_in[i]; break;  // 16*32
            case 1024:     if (nWh < 2) Wh[nWh++] = (const float*)d_in[i]; break;
            case 32:       if (nbh < 3) bh[nbh++] = (const float*)d_in[i]; break;
            case 33554432: Wfc1 = (const float*)d_in[i]; break;  // 131072*256
            case 256:      bfc1 = (const float*)d_in[i]; break;
            case 16384:    Wfc2 = (const float*)d_in[i]; break;  // 256*64
            case 64:       bfc2 = (const float*)d_in[i]; break;
            case 4194304:  ei   = d_in[i]; break;                // 2*E
            default: break;
        }
    }
    const float *W2 = Wh[0], *W3 = Wh[1];
    const float *b1 = bh[0], *b2 = bh[1], *b3 = bh[2];
    float* out = (float*)d_out;

    void *cntp, *fc1p, *hAp, *hBp;
    cudaGetSymbolAddress(&cntp, g_cnt);
    cudaGetSymbolAddress(&fc1p, g_fc1);
    cudaGetSymbolAddress(&hAp, g_hA);
    cudaGetSymbolAddress(&hBp, g_hB);

    // ---- CSR build (by dst) ----
    detect_dtype_kernel<<<1, 1024>>>((const unsigned int*)ei);
    cudaMemsetAsync(cntp, 0, (size_t)N_NODES * sizeof(int));
    count_kernel<<<E_EDGES / 256, 256>>>(ei);
    scan1_kernel<<<N_NODES / 1024, 1024>>>();
    scan2_kernel<<<N_NODES / 1024, 1024>>>();
    fill_kernel<<<E_EDGES / 256, 256>>>(ei, ea);

    // ---- layer 1: x[N,16] -> hA[N,32] ----
    agg_linear_kernel<16><<<N_NODES / 8, 256>>>(x, W1, b1, (float*)hAp);
    // ---- layer 2: hA -> hB ----
    agg_linear_kernel<32><<<N_NODES / 8, 256>>>((const float*)hAp, W2, b2, (float*)hBp);
    // ---- layer 3: hB -> hA ----
    agg_linear_kernel<32><<<N_NODES / 8, 256>>>((const float*)hBp, W3, b3, (float*)hAp);

    // ---- FC1 ----
    cudaMemsetAsync(fc1p, 0, (size_t)N_GRAPHS * FC_HID * sizeof(float));
    fc1_kernel<<<K_FC / TILE_K, 256>>>((const float*)hAp, Wfc1);

    // ---- FC2 -> output ----
    fc2_kernel<<<1, 1024>>>(bfc1, Wfc2, bfc2, out);
}